// round 13
// baseline (speedup 1.0000x reference)
#include <cuda_runtime.h>
#include <cuda_fp16.h>
#include <math_constants.h>
#include <cstdint>

// ---------------- scratch (__device__ globals; no allocations) -------------
__device__ __align__(16) __half g_A[40960 * 96];
__device__ __align__(16) __half g_BT[4096 * 96];
__device__ float g_pval[4][40960];
__device__ int   g_pidx[4][40960];
__device__ int   g_cnt[512];

__device__ __forceinline__ uint32_t smem_u32(const void* p) {
    uint32_t a;
    asm("{ .reg .u64 t; cvta.to.shared.u64 t, %1; cvt.u32.u64 %0, t; }" : "=r"(a) : "l"(p));
    return a;
}
__device__ __forceinline__ void ldmatrix_x4(uint32_t* r, uint32_t addr) {
    asm volatile("ldmatrix.sync.aligned.m8n8.x4.shared.b16 {%0,%1,%2,%3}, [%4];"
                 : "=r"(r[0]), "=r"(r[1]), "=r"(r[2]), "=r"(r[3]) : "r"(addr));
}
__device__ __forceinline__ void mma_f16(float* c, const uint32_t* a, const uint32_t* b) {
    asm volatile(
        "mma.sync.aligned.m16n8k16.row.col.f32.f16.f16.f32 "
        "{%0,%1,%2,%3}, {%4,%5,%6,%7}, {%8,%9}, {%0,%1,%2,%3};"
        : "+f"(c[0]), "+f"(c[1]), "+f"(c[2]), "+f"(c[3])
        : "r"(a[0]), "r"(a[1]), "r"(a[2]), "r"(a[3]), "r"(b[0]), "r"(b[1]));
}
__device__ __forceinline__ void cp16(uint32_t dst, const void* src) {
    asm volatile("cp.async.cg.shared.global [%0], [%1], 16;" :: "r"(dst), "l"(src));
}
#define CP_COMMIT() asm volatile("cp.async.commit_group;" ::: "memory")
#define CP_WAIT(n)  asm volatile("cp.async.wait_group %0;" :: "n"(n) : "memory")

// ---------------------------------------------------------------------------
// Fused prep, 512-thread blocks.
// Blocks [0,512): signs for batch b -> g_A (one 8-col chunk per thread);
//                 also zeroes g_cnt[b] for the fused stage2 trigger.
// Blocks [512,576): H1 2-term fp16 split for 64 n-rows -> g_BT.
// ---------------------------------------------------------------------------
__global__ __launch_bounds__(512)
void prep_kernel(const float* __restrict__ x,
                 const float* __restrict__ S1,
                 const float* __restrict__ T1,
                 const float* __restrict__ H1)
{
    const int tid = threadIdx.x;
    if (blockIdx.x < 512) {
        __shared__ __align__(16) float xs[480];
        __shared__ __align__(16) float s1s[900];
        __shared__ __align__(16) float t1s[450];
        const int b = blockIdx.x;
        if (tid == 511) g_cnt[b] = 0;
        if (tid < 480) xs[tid] = x[b * 480 + tid];
        for (int i = tid; i < 900; i += 512) s1s[i] = S1[i];
        if (tid < 450) t1s[tid] = T1[tid];
        __syncthreads();

        if (tid < 480) {
            const int row = tid / 6, ch = tid - row * 6;   // row = p*10+g
            const int p = row / 10, g = row - p * 10;
            uint4 w;
            __half2* hp = reinterpret_cast<__half2*>(&w);
#pragma unroll
            for (int e2 = 0; e2 < 4; e2++) {
                float sv[2];
#pragma unroll
                for (int h = 0; h < 2; h++) {
                    const int k = ch * 8 + e2 * 2 + h;
                    float s = 0.0f;
                    if (k < 45) {
                        const int j = g * 45 + k;
                        const int c = j / 15, kk = j - c * 15;
                        float vv = xs[p * 60 + 2 * c] * s1s[(2 * c) * 15 + kk];
                        vv = fmaf(xs[p * 60 + 2 * c + 1], s1s[(2 * c + 1) * 15 + kk], vv);
                        vv = vv - t1s[c * 15 + kk];
                        vv = vv - 1e-4f;
                        s = (vv > 0.0f) ? 1.0f : ((vv < 0.0f) ? -1.0f : 0.0f);
                    }
                    sv[h] = s;
                }
                hp[e2] = __halves2half2(__float2half_rn(sv[0]), __float2half_rn(sv[1]));
            }
            __half* dst = g_A + (size_t)(b * 80 + row) * 96 + ch * 8;
            *reinterpret_cast<uint4*>(dst)      = w;   // t = 0 copy
            *reinterpret_cast<uint4*>(dst + 48) = w;   // t = 1 copy
        }
    } else {
        __shared__ __align__(16) __half bs[64][104];
        const int n0 = (blockIdx.x - 512) * 64;
        const int nl = tid & 63;
        const int kg = tid >> 6;             // 0..7
#pragma unroll
        for (int kb = 0; kb < 48; kb += 8) {
            const int k = kb + kg;
            float h = 0.0f;
            if (k < 45) h = H1[(size_t)k * 4096 + n0 + nl];
            const __half a = __float2half_rn(h);
            bs[nl][k]      = a;
            bs[nl][48 + k] = __float2half_rn(h - __half2float(a));
        }
        __syncthreads();
        for (int v = tid; v < 768; v += 512) {
            const int row = v / 12, ch = v - row * 12;
            const uint4 w = *reinterpret_cast<const uint4*>(&bs[row][ch * 8]);
            *reinterpret_cast<uint4*>(g_BT + (size_t)(n0 + row) * 96 + ch * 8) = w;
        }
    }
}

// ---------------------------------------------------------------------------
// Main HMMA kernel with FUSED stage2. Grid 1280 = 320 mb x 4 nq, 256 threads.
// After writing its argmax slice, the last contributing CTA for batch row b
// runs the stage2 body for b inline (counter trigger in g_cnt).
// ---------------------------------------------------------------------------
static constexpr int ROWB    = 208;
static constexpr int TILE_B  = 128 * ROWB;             // 26624
static constexpr int SM_A    = 0;
static constexpr int SM_B    = TILE_B;
static constexpr int SM_RED  = 3 * TILE_B;             // 79872
static constexpr int SMEM_BYTES = SM_RED + 4096;       // 83968

__global__ __launch_bounds__(256, 2)
void mma_kernel(const float* __restrict__ LUT1,
                const float* __restrict__ S2,
                const float* __restrict__ H2,
                const float* __restrict__ T2,
                const float* __restrict__ LUT2,
                float* __restrict__ out)
{
    extern __shared__ __align__(16) char smem[];
    const uint32_t sb = smem_u32(smem);
    float* sval = reinterpret_cast<float*>(smem + SM_RED);
    int*   sidx = reinterpret_cast<int*>(smem + SM_RED + 2048);

    const int tid = threadIdx.x;
    const int wid = tid >> 5;
    const int l   = tid & 31;
    const int q   = l & 3;
    const int wx  = wid >> 2;
    const int wy  = wid & 3;
    const int mb  = blockIdx.x >> 2;   // 0..319
    const int nq  = blockIdx.x & 3;    // 0..3

    // ---- prologue: A tile + B tile 0 via cp.async ----
    {
        const size_t m0 = (size_t)mb * 128;
#pragma unroll
        for (int i = 0; i < 6; i++) {
            const int v = tid + i * 256;
            const int row = v / 12, ch = v - row * 12;
            cp16(sb + SM_A + row * ROWB + ch * 16, g_A + (m0 + row) * 96 + ch * 8);
        }
        const size_t n0 = (size_t)nq * 1024;
#pragma unroll
        for (int i = 0; i < 6; i++) {
            const int v = tid + i * 256;
            const int row = v / 12, ch = v - row * 12;
            cp16(sb + SM_B + row * ROWB + ch * 16, g_BT + (n0 + row) * 96 + ch * 8);
        }
        CP_COMMIT();
    }

    uint32_t a_addr[4], b_addr[2];
#pragma unroll
    for (int mt = 0; mt < 4; mt++) {
        const int r = wx * 64 + mt * 16 + (l & 7) + 8 * ((l >> 3) & 1);
        a_addr[mt] = sb + SM_A + r * ROWB + (l >> 4) * 16;
    }
#pragma unroll
    for (int p2 = 0; p2 < 2; p2++) {
        const int n = wy * 32 + p2 * 16 + ((l >> 4) & 1) * 8 + (l & 7);
        b_addr[p2] = sb + SM_B + n * ROWB + ((l >> 3) & 1) * 16;
    }

    float rv[8];
    int   ri[8];
#pragma unroll
    for (int s = 0; s < 8; s++) { rv[s] = -CUDART_INF_F; ri[s] = 0; }

#pragma unroll 1
    for (int it = 0; it < 8; it++) {
        const int n0 = nq * 1024 + it * 128;

        if (it < 7) {
            const size_t nn = (size_t)nq * 1024 + (it + 1) * 128;
            const uint32_t bufo = ((it + 1) & 1) * TILE_B;
#pragma unroll
            for (int i = 0; i < 6; i++) {
                const int v = tid + i * 256;
                const int row = v / 12, ch = v - row * 12;
                cp16(sb + SM_B + bufo + row * ROWB + ch * 16,
                     g_BT + (nn + row) * 96 + ch * 8);
            }
            CP_COMMIT();
            CP_WAIT(1);
        } else {
            CP_WAIT(0);
        }
        __syncthreads();

        const uint32_t boff = (it & 1) * TILE_B;

        float acc[4][4][4];
#pragma unroll
        for (int mt = 0; mt < 4; mt++)
#pragma unroll
            for (int nt = 0; nt < 4; nt++) {
                acc[mt][nt][0] = 0.f; acc[mt][nt][1] = 0.f;
                acc[mt][nt][2] = 0.f; acc[mt][nt][3] = 0.f;
            }

#pragma unroll
        for (int ks = 0; ks < 6; ks++) {
            uint32_t af[4][4], bf[4][2];
#pragma unroll
            for (int mt = 0; mt < 4; mt++) ldmatrix_x4(af[mt], a_addr[mt] + ks * 32);
#pragma unroll
            for (int p2 = 0; p2 < 2; p2++) {
                uint32_t t4[4];
                ldmatrix_x4(t4, b_addr[p2] + boff + ks * 32);
                bf[2 * p2 + 0][0] = t4[0]; bf[2 * p2 + 0][1] = t4[1];
                bf[2 * p2 + 1][0] = t4[2]; bf[2 * p2 + 1][1] = t4[3];
            }
#pragma unroll
            for (int mt = 0; mt < 4; mt++)
#pragma unroll
                for (int nt = 0; nt < 4; nt++)
                    mma_f16(acc[mt][nt], af[mt], bf[nt]);
        }

#pragma unroll
        for (int mt = 0; mt < 4; mt++) {
#pragma unroll
            for (int nt = 0; nt < 4; nt++) {
                const int col0 = n0 + wy * 32 + nt * 8 + 2 * q;
                const int s0 = mt * 2, s1 = mt * 2 + 1;
                if (acc[mt][nt][0] > rv[s0]) { rv[s0] = acc[mt][nt][0]; ri[s0] = col0; }
                if (acc[mt][nt][1] > rv[s0]) { rv[s0] = acc[mt][nt][1]; ri[s0] = col0 + 1; }
                if (acc[mt][nt][2] > rv[s1]) { rv[s1] = acc[mt][nt][2]; ri[s1] = col0; }
                if (acc[mt][nt][3] > rv[s1]) { rv[s1] = acc[mt][nt][3]; ri[s1] = col0 + 1; }
            }
        }
        __syncthreads();
    }

    // ---- reduce over lanes sharing each row, idx tiebreak ----
#pragma unroll
    for (int off = 1; off <= 2; off <<= 1) {
#pragma unroll
        for (int s = 0; s < 8; s++) {
            const float ov = __shfl_xor_sync(0xffffffffu, rv[s], off);
            const int   oi = __shfl_xor_sync(0xffffffffu, ri[s], off);
            if (ov > rv[s] || (ov == rv[s] && oi < ri[s])) { rv[s] = ov; ri[s] = oi; }
        }
    }
    if (q == 0) {
#pragma unroll
        for (int mt = 0; mt < 4; mt++) {
#pragma unroll
            for (int half = 0; half < 2; half++) {
                const int row = wx * 64 + mt * 16 + 8 * half + (l >> 2);
                sval[wy * 128 + row] = rv[mt * 2 + half];
                sidx[wy * 128 + row] = ri[mt * 2 + half];
            }
        }
    }
    __syncthreads();

    if (tid < 128) {
        float bv = sval[tid];
        int   bi = sidx[tid];
#pragma unroll
        for (int w = 1; w < 4; w++) {
            const float ov = sval[w * 128 + tid];
            const int   oi = sidx[w * 128 + tid];
            if (ov > bv || (ov == bv && oi < bi)) { bv = ov; bi = oi; }
        }
        g_pval[nq][mb * 128 + tid] = bv;
        g_pidx[nq][mb * 128 + tid] = bi;
    }
    __syncthreads();   // all g_pval/g_pidx writes issued; sval/sidx reusable

    // ---- fused stage2 trigger ----
    __shared__ int s_go;
    // stage2 scratch aliased over the reduction region (no longer needed)
    float* lutv   = reinterpret_cast<float*>(smem + SM_RED);          // [8][10][2]
    float* zz     = reinterpret_cast<float*>(smem + SM_RED + 640);    // [16]
    int*   sidx2  = reinterpret_cast<int*>(smem + SM_RED + 704);      // [8]
    float* logits = reinterpret_cast<float*>(smem + SM_RED + 736);    // [100]
    float* lse    = reinterpret_cast<float*>(smem + SM_RED + 1136);   // [1]

    if (tid == 0) { asm volatile("membar.gl;" ::: "memory"); }

    const int b_lo = (mb * 128) / 80;
    const int b_hi = (mb * 128 + 127) / 80;

#pragma unroll 1
    for (int bb = b_lo; bb <= b_hi; bb++) {
        if (tid == 0) {
            const int t_need = (((80 * bb + 79) >> 7) - ((80 * bb) >> 7) + 1) * 4;
            const int prev = atomicAdd(&g_cnt[bb], 1);
            int go = (prev == t_need - 1) ? 1 : 0;
            if (go) { asm volatile("membar.gl;" ::: "memory"); }
            s_go = go;
        }
        __syncthreads();
        if (s_go) {
            // ---- stage2 body for batch row bb (identical math/order) ----
            if (tid < 80) {
                const int p = tid / 10, g = tid - p * 10;
                const int m = (bb * 8 + p) * 10 + g;
                float bv = __ldcg(&g_pval[0][m]);
                int   bi = __ldcg(&g_pidx[0][m]);
#pragma unroll
                for (int qq = 1; qq < 4; qq++) {
                    const float v = __ldcg(&g_pval[qq][m]);
                    if (v > bv) { bv = v; bi = __ldcg(&g_pidx[qq][m]); }
                }
                lutv[(p * 10 + g) * 2 + 0] = LUT1[(g * 4096 + bi) * 2 + 0];
                lutv[(p * 10 + g) * 2 + 1] = LUT1[(g * 4096 + bi) * 2 + 1];
            }
            __syncthreads();

            if (tid < 16) {
                const int p = tid >> 1, d = tid & 1;
                float acc2 = 0.0f;
#pragma unroll
                for (int g = 0; g < 10; g++) acc2 += lutv[(p * 10 + g) * 2 + d];
                zz[p * 2 + d] = acc2;
            }
            __syncthreads();

            if (tid < 8) {
                const int c = tid;
                float w[15];
#pragma unroll
                for (int k = 0; k < 15; k++) {
                    float v = zz[2 * c + 0] * S2[(c * 2 + 0) * 15 + k];
                    v = fmaf(zz[2 * c + 1], S2[(c * 2 + 1) * 15 + k], v);
                    v = v - T2[c * 15 + k];
                    w[k] = (v > 0.0f) ? 1.0f : -1.0f;
                }
                float bm = -CUDART_INF_F;
                int   bi = 0;
#pragma unroll
                for (int m = 0; m < 16; m++) {
                    float sc = 0.0f;
#pragma unroll
                    for (int k = 0; k < 15; k++) sc = fmaf(w[k], H2[k * 16 + m], sc);
                    if (sc > bm) { bm = sc; bi = m; }
                }
                sidx2[c] = bi;
            }
            __syncthreads();

            if (tid < 100) {
                float lsum = 0.0f;
#pragma unroll
                for (int c = 0; c < 8; c++) lsum += LUT2[(c * 16 + sidx2[c]) * 100 + tid];
                logits[tid] = lsum;
            }
            __syncthreads();

            if (tid == 0) {
                float mx = logits[0];
                for (int m = 1; m < 100; m++) mx = fmaxf(mx, logits[m]);
                float s = 0.0f;
                for (int m = 0; m < 100; m++) s += expf(logits[m] - mx);
                lse[0] = mx + logf(s);
            }
            __syncthreads();

            if (tid < 100) out[bb * 100 + tid] = logits[tid] - lse[0];
        }
        __syncthreads();
    }
}

// ---------------------------------------------------------------------------
extern "C" void kernel_launch(void* const* d_in, const int* in_sizes, int n_in,
                              void* d_out, int out_size)
{
    const float* x    = (const float*)d_in[0];
    const float* S1   = (const float*)d_in[1];
    const float* H1   = (const float*)d_in[2];
    const float* T1   = (const float*)d_in[3];
    const float* LUT1 = (const float*)d_in[4];
    const float* S2   = (const float*)d_in[5];
    const float* H2   = (const float*)d_in[6];
    const float* T2   = (const float*)d_in[7];
    const float* LUT2 = (const float*)d_in[8];
    float* out = (float*)d_out;

    static bool attr_set = false;
    if (!attr_set) {
        cudaFuncSetAttribute(mma_kernel, cudaFuncAttributeMaxDynamicSharedMemorySize,
                             SMEM_BYTES);
        attr_set = true;
    }

    prep_kernel<<<576, 512>>>(x, S1, T1, H1);
    mma_kernel<<<1280, 256, SMEM_BYTES>>>(LUT1, S2, H2, T2, LUT2, out);
}

// round 14
// speedup vs baseline: 1.2525x; 1.2525x over previous
#include <cuda_runtime.h>
#include <cuda_fp16.h>
#include <math_constants.h>
#include <cstdint>

// ---------------- scratch (__device__ globals; no allocations) -------------
__device__ __align__(16) __half g_A[40960 * 96];
__device__ __align__(16) __half g_BT[4096 * 96];
__device__ float g_pval[4][40960];
__device__ int   g_pidx[4][40960];

__device__ __forceinline__ uint32_t smem_u32(const void* p) {
    uint32_t a;
    asm("{ .reg .u64 t; cvta.to.shared.u64 t, %1; cvt.u32.u64 %0, t; }" : "=r"(a) : "l"(p));
    return a;
}
__device__ __forceinline__ void ldmatrix_x4(uint32_t* r, uint32_t addr) {
    asm volatile("ldmatrix.sync.aligned.m8n8.x4.shared.b16 {%0,%1,%2,%3}, [%4];"
                 : "=r"(r[0]), "=r"(r[1]), "=r"(r[2]), "=r"(r[3]) : "r"(addr));
}
__device__ __forceinline__ void mma_f16(float* c, const uint32_t* a, const uint32_t* b) {
    asm volatile(
        "mma.sync.aligned.m16n8k16.row.col.f32.f16.f16.f32 "
        "{%0,%1,%2,%3}, {%4,%5,%6,%7}, {%8,%9}, {%0,%1,%2,%3};"
        : "+f"(c[0]), "+f"(c[1]), "+f"(c[2]), "+f"(c[3])
        : "r"(a[0]), "r"(a[1]), "r"(a[2]), "r"(a[3]), "r"(b[0]), "r"(b[1]));
}
__device__ __forceinline__ void cp16(uint32_t dst, const void* src) {
    asm volatile("cp.async.cg.shared.global [%0], [%1], 16;" :: "r"(dst), "l"(src));
}
#define CP_COMMIT() asm volatile("cp.async.commit_group;" ::: "memory")
#define CP_WAIT(n)  asm volatile("cp.async.wait_group %0;" :: "n"(n) : "memory")

// ---------------------------------------------------------------------------
// Fused prep, 512-thread blocks (R12, unchanged).
// ---------------------------------------------------------------------------
__global__ __launch_bounds__(512)
void prep_kernel(const float* __restrict__ x,
                 const float* __restrict__ S1,
                 const float* __restrict__ T1,
                 const float* __restrict__ H1)
{
    const int tid = threadIdx.x;
    if (blockIdx.x < 512) {
        __shared__ __align__(16) float xs[480];
        __shared__ __align__(16) float s1s[900];
        __shared__ __align__(16) float t1s[450];
        const int b = blockIdx.x;
        if (tid < 480) xs[tid] = x[b * 480 + tid];
        for (int i = tid; i < 900; i += 512) s1s[i] = S1[i];
        if (tid < 450) t1s[tid] = T1[tid];
        __syncthreads();

        if (tid < 480) {
            const int row = tid / 6, ch = tid - row * 6;   // row = p*10+g
            const int p = row / 10, g = row - p * 10;
            uint4 w;
            __half2* hp = reinterpret_cast<__half2*>(&w);
#pragma unroll
            for (int e2 = 0; e2 < 4; e2++) {
                float sv[2];
#pragma unroll
                for (int h = 0; h < 2; h++) {
                    const int k = ch * 8 + e2 * 2 + h;
                    float s = 0.0f;
                    if (k < 45) {
                        const int j = g * 45 + k;
                        const int c = j / 15, kk = j - c * 15;
                        float vv = xs[p * 60 + 2 * c] * s1s[(2 * c) * 15 + kk];
                        vv = fmaf(xs[p * 60 + 2 * c + 1], s1s[(2 * c + 1) * 15 + kk], vv);
                        vv = vv - t1s[c * 15 + kk];
                        vv = vv - 1e-4f;
                        s = (vv > 0.0f) ? 1.0f : ((vv < 0.0f) ? -1.0f : 0.0f);
                    }
                    sv[h] = s;
                }
                hp[e2] = __halves2half2(__float2half_rn(sv[0]), __float2half_rn(sv[1]));
            }
            __half* dst = g_A + (size_t)(b * 80 + row) * 96 + ch * 8;
            *reinterpret_cast<uint4*>(dst)      = w;
            *reinterpret_cast<uint4*>(dst + 48) = w;
        }
    } else {
        __shared__ __align__(16) __half bs[64][104];
        const int n0 = (blockIdx.x - 512) * 64;
        const int nl = tid & 63;
        const int kg = tid >> 6;             // 0..7
#pragma unroll
        for (int kb = 0; kb < 48; kb += 8) {
            const int k = kb + kg;
            float h = 0.0f;
            if (k < 45) h = H1[(size_t)k * 4096 + n0 + nl];
            const __half a = __float2half_rn(h);
            bs[nl][k]      = a;
            bs[nl][48 + k] = __float2half_rn(h - __half2float(a));
        }
        __syncthreads();
        for (int v = tid; v < 768; v += 512) {
            const int row = v / 12, ch = v - row * 12;
            const uint4 w = *reinterpret_cast<const uint4*>(&bs[row][ch * 8]);
            *reinterpret_cast<uint4*>(g_BT + (size_t)(n0 + row) * 96 + ch * 8) = w;
        }
    }
}

// ---------------------------------------------------------------------------
// Main HMMA kernel, occupancy-3 shape. Grid 1280 = 320 mb x 4 nq, 256 thr.
// CTA tile 128M x 64N per iter, 16 N-iters. Warps 4x2 (warp tile 32x32).
// acc = 32 regs/thread -> 3 CTAs/SM. A resident; B (64 rows) double-buffered.
// ---------------------------------------------------------------------------
static constexpr int ROWB    = 208;
static constexpr int TILE_A  = 128 * ROWB;             // 26624
static constexpr int TILE_B  = 64 * ROWB;              // 13312
static constexpr int SM_A    = 0;
static constexpr int SM_B    = TILE_A;                 // buf0; buf1 at +TILE_B
static constexpr int SM_RED  = TILE_A + 2 * TILE_B;    // 53248
static constexpr int SMEM_BYTES = SM_RED + 2048;       // 55296

__global__ __launch_bounds__(256, 3)
void mma_kernel()
{
    extern __shared__ __align__(16) char smem[];
    const uint32_t sb = smem_u32(smem);
    float* sval = reinterpret_cast<float*>(smem + SM_RED);
    int*   sidx = reinterpret_cast<int*>(smem + SM_RED + 1024);

    const int tid = threadIdx.x;
    const int wid = tid >> 5;
    const int l   = tid & 31;
    const int q   = l & 3;
    const int wx  = wid >> 1;          // 0..3 (M quarter, 32 rows)
    const int wy  = wid & 1;           // 0..1 (N half, 32 cols)
    const int mb  = blockIdx.x >> 2;   // 0..319
    const int nq  = blockIdx.x & 3;    // 0..3

    // ---- prologue: A tile (1536 chunks) + B tile 0 (768 chunks) ----
    {
        const size_t m0 = (size_t)mb * 128;
#pragma unroll
        for (int i = 0; i < 6; i++) {
            const int v = tid + i * 256;
            const int row = v / 12, ch = v - row * 12;
            cp16(sb + SM_A + row * ROWB + ch * 16, g_A + (m0 + row) * 96 + ch * 8);
        }
        const size_t n0 = (size_t)nq * 1024;
#pragma unroll
        for (int i = 0; i < 3; i++) {
            const int v = tid + i * 256;
            const int row = v / 12, ch = v - row * 12;
            cp16(sb + SM_B + row * ROWB + ch * 16, g_BT + (n0 + row) * 96 + ch * 8);
        }
        CP_COMMIT();
    }

    // ldmatrix base addresses (k advances +32B per k-step)
    uint32_t a_addr[2], b_addr[2];
#pragma unroll
    for (int mt = 0; mt < 2; mt++) {
        const int r = wx * 32 + mt * 16 + (l & 7) + 8 * ((l >> 3) & 1);
        a_addr[mt] = sb + SM_A + r * ROWB + (l >> 4) * 16;
    }
#pragma unroll
    for (int p2 = 0; p2 < 2; p2++) {
        // x4 B load: lane groups 0-7/8-15 -> nt=2*p2 (k halves), 16-31 -> nt=2*p2+1
        const int n = wy * 32 + p2 * 16 + ((l >> 4) & 1) * 8 + (l & 7);
        b_addr[p2] = n * ROWB + ((l >> 3) & 1) * 16;   // buffer-relative
    }

    float rv[4];
    int   ri[4];
#pragma unroll
    for (int s = 0; s < 4; s++) { rv[s] = -CUDART_INF_F; ri[s] = 0; }

#pragma unroll 1
    for (int it = 0; it < 16; it++) {
        const int n0 = nq * 1024 + it * 64;

        if (it < 15) {
            const size_t nn = (size_t)nq * 1024 + (it + 1) * 64;
            const uint32_t bufo = ((it + 1) & 1) * TILE_B;
#pragma unroll
            for (int i = 0; i < 3; i++) {
                const int v = tid + i * 256;
                const int row = v / 12, ch = v - row * 12;
                cp16(sb + SM_B + bufo + row * ROWB + ch * 16,
                     g_BT + (nn + row) * 96 + ch * 8);
            }
            CP_COMMIT();
            CP_WAIT(1);
        } else {
            CP_WAIT(0);
        }
        __syncthreads();

        const uint32_t bbase = sb + SM_B + (it & 1) * TILE_B;

        float acc[2][4][4];
#pragma unroll
        for (int mt = 0; mt < 2; mt++)
#pragma unroll
            for (int nt = 0; nt < 4; nt++) {
                acc[mt][nt][0] = 0.f; acc[mt][nt][1] = 0.f;
                acc[mt][nt][2] = 0.f; acc[mt][nt][3] = 0.f;
            }

#pragma unroll
        for (int ks = 0; ks < 6; ks++) {
            uint32_t af[2][4], bf[4][2];
#pragma unroll
            for (int mt = 0; mt < 2; mt++) ldmatrix_x4(af[mt], a_addr[mt] + ks * 32);
#pragma unroll
            for (int p2 = 0; p2 < 2; p2++) {
                uint32_t t4[4];
                ldmatrix_x4(t4, bbase + b_addr[p2] + ks * 32);
                bf[2 * p2 + 0][0] = t4[0]; bf[2 * p2 + 0][1] = t4[1];
                bf[2 * p2 + 1][0] = t4[2]; bf[2 * p2 + 1][1] = t4[3];
            }
#pragma unroll
            for (int mt = 0; mt < 2; mt++)
#pragma unroll
                for (int nt = 0; nt < 4; nt++)
                    mma_f16(acc[mt][nt], af[mt], bf[nt]);
        }

        // running argmax (c0:(row l/4,col 2q), c1:+1col, c2/3:+8row)
#pragma unroll
        for (int mt = 0; mt < 2; mt++) {
#pragma unroll
            for (int nt = 0; nt < 4; nt++) {
                const int col0 = n0 + wy * 32 + nt * 8 + 2 * q;
                const int s0 = mt * 2, s1 = mt * 2 + 1;
                if (acc[mt][nt][0] > rv[s0]) { rv[s0] = acc[mt][nt][0]; ri[s0] = col0; }
                if (acc[mt][nt][1] > rv[s0]) { rv[s0] = acc[mt][nt][1]; ri[s0] = col0 + 1; }
                if (acc[mt][nt][2] > rv[s1]) { rv[s1] = acc[mt][nt][2]; ri[s1] = col0; }
                if (acc[mt][nt][3] > rv[s1]) { rv[s1] = acc[mt][nt][3]; ri[s1] = col0 + 1; }
            }
        }
        __syncthreads();   // compute done before next iter overwrites this buffer
    }

    // ---- reduce over the 4 lanes sharing each row, idx tiebreak ----
#pragma unroll
    for (int off = 1; off <= 2; off <<= 1) {
#pragma unroll
        for (int s = 0; s < 4; s++) {
            const float ov = __shfl_xor_sync(0xffffffffu, rv[s], off);
            const int   oi = __shfl_xor_sync(0xffffffffu, ri[s], off);
            if (ov > rv[s] || (ov == rv[s] && oi < ri[s])) { rv[s] = ov; ri[s] = oi; }
        }
    }
    if (q == 0) {
#pragma unroll
        for (int mt = 0; mt < 2; mt++) {
#pragma unroll
            for (int half = 0; half < 2; half++) {
                const int row = wx * 32 + mt * 16 + 8 * half + (l >> 2);
                sval[wy * 128 + row] = rv[mt * 2 + half];
                sidx[wy * 128 + row] = ri[mt * 2 + half];
            }
        }
    }
    __syncthreads();

    if (tid < 128) {
        // merge the 2 N-halves: value desc, index asc on ties (first occurrence)
        float bv = sval[tid];
        int   bi = sidx[tid];
        const float ov = sval[128 + tid];
        const int   oi = sidx[128 + tid];
        if (ov > bv || (ov == bv && oi < bi)) { bv = ov; bi = oi; }
        g_pval[nq][mb * 128 + tid] = bv;
        g_pidx[nq][mb * 128 + tid] = bi;
    }
}

// ---------------------------------------------------------------------------
// Stage 2 (R12 shape): two batch rows per 256-thread block. Grid 256.
// ---------------------------------------------------------------------------
__global__ __launch_bounds__(256, 4)
void stage2_kernel(const float* __restrict__ LUT1,
                   const float* __restrict__ S2,
                   const float* __restrict__ H2,
                   const float* __restrict__ T2,
                   const float* __restrict__ LUT2,
                   float* __restrict__ out)
{
    __shared__ float lutv[2][8][10][2];
    __shared__ float z[2][16];
    __shared__ int   sidx2[2][8];
    __shared__ float logits[2][100];
    __shared__ float s_lse[2];

    const int tid  = threadIdx.x;
    const int half = tid >> 7;
    const int ltid = tid & 127;
    const int b    = blockIdx.x * 2 + half;

    if (ltid < 80) {
        const int p = ltid / 10, g = ltid - p * 10;
        const int m = (b * 8 + p) * 10 + g;
        float bv = g_pval[0][m];
        int   bi = g_pidx[0][m];
#pragma unroll
        for (int qq = 1; qq < 4; qq++) {
            const float v = g_pval[qq][m];
            if (v > bv) { bv = v; bi = g_pidx[qq][m]; }
        }
        lutv[half][p][g][0] = LUT1[(g * 4096 + bi) * 2 + 0];
        lutv[half][p][g][1] = LUT1[(g * 4096 + bi) * 2 + 1];
    }
    __syncthreads();

    if (ltid < 16) {
        const int p = ltid >> 1, d = ltid & 1;
        float acc = 0.0f;
#pragma unroll
        for (int g = 0; g < 10; g++) acc += lutv[half][p][g][d];
        z[half][p * 2 + d] = acc;
    }
    __syncthreads();

    if (ltid < 8) {
        const int c = ltid;
        float w[15];
#pragma unroll
        for (int k = 0; k < 15; k++) {
            float v = z[half][2 * c + 0] * S2[(c * 2 + 0) * 15 + k];
            v = fmaf(z[half][2 * c + 1], S2[(c * 2 + 1) * 15 + k], v);
            v = v - T2[c * 15 + k];
            w[k] = (v > 0.0f) ? 1.0f : -1.0f;
        }
        float bm = -CUDART_INF_F;
        int   bi = 0;
#pragma unroll
        for (int m = 0; m < 16; m++) {
            float sc = 0.0f;
#pragma unroll
            for (int k = 0; k < 15; k++) sc = fmaf(w[k], H2[k * 16 + m], sc);
            if (sc > bm) { bm = sc; bi = m; }
        }
        sidx2[half][c] = bi;
    }
    __syncthreads();

    if (ltid < 100) {
        float lsum = 0.0f;
#pragma unroll
        for (int c = 0; c < 8; c++) lsum += LUT2[(c * 16 + sidx2[half][c]) * 100 + ltid];
        logits[half][ltid] = lsum;
    }
    __syncthreads();

    if (ltid == 0) {
        float mx = logits[half][0];
        for (int m = 1; m < 100; m++) mx = fmaxf(mx, logits[half][m]);
        float s = 0.0f;
        for (int m = 0; m < 100; m++) s += expf(logits[half][m] - mx);
        s_lse[half] = mx + logf(s);
    }
    __syncthreads();

    if (ltid < 100) out[b * 100 + ltid] = logits[half][ltid] - s_lse[half];
}

// ---------------------------------------------------------------------------
extern "C" void kernel_launch(void* const* d_in, const int* in_sizes, int n_in,
                              void* d_out, int out_size)
{
    const float* x    = (const float*)d_in[0];
    const float* S1   = (const float*)d_in[1];
    const float* H1   = (const float*)d_in[2];
    const float* T1   = (const float*)d_in[3];
    const float* LUT1 = (const float*)d_in[4];
    const float* S2   = (const float*)d_in[5];
    const float* H2   = (const float*)d_in[6];
    const float* T2   = (const float*)d_in[7];
    const float* LUT2 = (const float*)d_in[8];
    float* out = (float*)d_out;

    static bool attr_set = false;
    if (!attr_set) {
        cudaFuncSetAttribute(mma_kernel, cudaFuncAttributeMaxDynamicSharedMemorySize,
                             SMEM_BYTES);
        attr_set = true;
    }

    prep_kernel<<<576, 512>>>(x, S1, T1, H1);
    mma_kernel<<<1280, 256, SMEM_BYTES>>>();
    stage2_kernel<<<256, 256>>>(LUT1, S2, H2, T2, LUT2, out);
}